// round 5
// baseline (speedup 1.0000x reference)
#include <cuda_runtime.h>
#include <cstdint>

// Problem constants (from reference): B=8, N=65536, C=256, NPOINT=1024
#define BB        8
#define NN        65536
#define CC        256
#define NPOINTS   1024
#define CHUNKS    16                  // blocks per batch (16*8=128 blocks, all resident wave-1)
#define TFPS      512                 // threads per FPS block
#define PPB       (NN / CHUNKS)       // 4096 points per block
#define PPT       (PPB / TFPS)        // 8 points per thread

// Mailbox: one 64-bit packed value per (batch, iter, chunk); fresh slot per
// iteration -> no phase hazards. Packed value is always nonzero (the low word
// holds ~idx >= 0xFFFF0000), so 0 == "not yet written". Self-contained 8-byte
// payload -> no memory fences needed anywhere.
__device__ unsigned long long g_part[BB][NPOINTS][CHUNKS];
__device__ int                g_inds[BB][NPOINTS];

struct InitFar { int v[BB]; };

__device__ __forceinline__ unsigned long long ld_relaxed_u64(const unsigned long long* p) {
    unsigned long long v;
    asm volatile("ld.relaxed.gpu.u64 %0, [%1];" : "=l"(v) : "l"(p) : "memory");
    return v;
}
__device__ __forceinline__ void st_relaxed_u64(unsigned long long* p, unsigned long long v) {
    asm volatile("st.relaxed.gpu.u64 [%0], %1;" :: "l"(p), "l"(v) : "memory");
}

// ---------------------------------------------------------------------------
// Zero the mailbox (scratch persists across graph replays -> must reset)
// ---------------------------------------------------------------------------
__global__ void init_kernel() {
    const int total = BB * NPOINTS * CHUNKS;
    unsigned long long* base = &g_part[0][0][0];
    for (int i = blockIdx.x * blockDim.x + threadIdx.x; i < total; i += gridDim.x * blockDim.x)
        base[i] = 0ull;
}

// ---------------------------------------------------------------------------
// FPS: one batch split across CHUNKS blocks; points + running distances live
// in registers. Per iteration:
//   local min-update + argmax  ->  warp reduce  ->  block combine (t0)
//   t0 publishes packed best to its mailbox slot (relaxed store)
//   t0 polls ALL 16 slots itself (MLP=16, distinct lines -> no hot spot),
//   reduces locally, broadcasts winner via shared + the single __syncthreads.
// No atomics, no fences, no nanosleep, no global broadcast line.
// Packing: (float_bits(dist) << 32) | ~idx  -> max picks largest dist, and on
// ties the SMALLEST index (matches jnp.argmax first-occurrence semantics).
// ---------------------------------------------------------------------------
__global__ __launch_bounds__(TFPS, 1)
void fps_kernel(const float* __restrict__ xyz, InitFar init) {
    const int b     = blockIdx.y;
    const int chunk = blockIdx.x;
    const int t     = threadIdx.x;
    const int lane  = t & 31;
    const int warp  = t >> 5;
    const int base  = chunk * PPB;

    const float* __restrict__ xb = xyz + (size_t)b * NN * 3;

    float    px[PPT], py[PPT], pz[PPT], dist[PPT];
    unsigned ienc[PPT];
#pragma unroll
    for (int k = 0; k < PPT; ++k) {
        const int p = base + k * TFPS + t;
        const float* q = xb + 3 * (size_t)p;
        px[k] = q[0]; py[k] = q[1]; pz[k] = q[2];
        dist[k] = 1e10f;
        ienc[k] = ~(unsigned)p;
    }

    __shared__ unsigned long long s_red[TFPS / 32];
    __shared__ int s_far;

    int far = init.v[b];

    for (int it = 0; it < NPOINTS; ++it) {
        // Record the index chosen at the START of the step (matches lax.scan ys)
        if (chunk == 0 && t == 0) g_inds[b][it] = far;

        // Centroid broadcast load (first warp misses to L2, rest hit L1)
        const float* cq = xb + 3 * (size_t)far;
        const float cx = __ldg(cq + 0);
        const float cy = __ldg(cq + 1);
        const float cz = __ldg(cq + 2);

        unsigned long long best = 0ull;
#pragma unroll
        for (int k = 0; k < PPT; ++k) {
            // Match XLA (no FP contraction): sub, mul, (d0+d1)+d2, all round-to-nearest
            const float dx = __fsub_rn(px[k], cx);
            const float dy = __fsub_rn(py[k], cy);
            const float dz = __fsub_rn(pz[k], cz);
            const float d  = __fadd_rn(__fadd_rn(__fmul_rn(dx, dx), __fmul_rn(dy, dy)),
                                       __fmul_rn(dz, dz));
            const float nd = fminf(dist[k], d);
            dist[k] = nd;
            const unsigned long long pk =
                ((unsigned long long)__float_as_uint(nd) << 32) | (unsigned long long)ienc[k];
            best = (best < pk) ? pk : best;
        }

        // Warp reduce (max)
#pragma unroll
        for (int off = 16; off > 0; off >>= 1) {
            const unsigned long long o = __shfl_xor_sync(0xFFFFFFFFu, best, off);
            best = (best < o) ? o : best;
        }
        if (lane == 0) s_red[warp] = best;
        __syncthreads();

        if (t == 0) {
            // Block combine
            unsigned long long blk = s_red[0];
#pragma unroll
            for (int i = 1; i < TFPS / 32; ++i) blk = (blk < s_red[i]) ? s_red[i] : blk;

            // Publish to this chunk's slot (single relaxed store; payload is
            // self-contained so no fence is required)
            st_relaxed_u64(&g_part[b][it][chunk], blk);

            // Redundantly poll all CHUNKS slots with full MLP; each round is
            // ~one L2 latency since all 16 loads are independent lines.
            unsigned long long v[CHUNKS];
            for (;;) {
                unsigned long long prod = 0xFFFFFFFFFFFFFFFFull;
#pragma unroll
                for (int i = 0; i < CHUNKS; ++i) {
                    v[i] = ld_relaxed_u64(&g_part[b][it][i]);
                    prod &= (v[i] != 0ull) ? 0xFFFFFFFFFFFFFFFFull : 0ull;
                }
                if (prod) break;
            }
            unsigned long long w = v[0];
#pragma unroll
            for (int i = 1; i < CHUNKS; ++i) w = (w < v[i]) ? v[i] : w;

            s_far = (int)(~(unsigned)(w & 0xFFFFFFFFull));
        }
        __syncthreads();
        far = s_far;
    }
}

// ---------------------------------------------------------------------------
// Gather outputs. d_out (float32) layout, concatenated in reference order:
//   [0)                    new_xyz      (B, NPOINT, 3)
//   [B*NPOINT*3)           new_features (B, C, NPOINT)
//   [.. + B*C*NPOINT)      sample_inds  (B, NPOINT)  (indices as float)
// ---------------------------------------------------------------------------
__global__ void gather_kernel(const float* __restrict__ xyz,
                              const float* __restrict__ feat,
                              float* __restrict__ out) {
    const int b = blockIdx.x;
    const int c = blockIdx.y;

    float* out_xyz  = out;
    float* out_feat = out + (size_t)BB * NPOINTS * 3;
    float* out_inds = out_feat + (size_t)BB * CC * NPOINTS;

    const float* frow = feat + ((size_t)b * CC + c) * NN;
    float*       orow = out_feat + ((size_t)b * CC + c) * NPOINTS;

    for (int j = threadIdx.x; j < NPOINTS; j += blockDim.x) {
        const int idx = g_inds[b][j];
        orow[j] = frow[idx];
        if (c == 0) {
            out_inds[(size_t)b * NPOINTS + j] = (float)idx;
            const float* q = xyz + ((size_t)b * NN + idx) * 3;
            float* o = out_xyz + ((size_t)b * NPOINTS + j) * 3;
            o[0] = q[0]; o[1] = q[1]; o[2] = q[2];
        }
    }
}

// ---------------------------------------------------------------------------
// Host: reproduce jax.random.randint(jax.random.key(1), (8,), 0, 65536)
// under jax_threefry_partitionable=True (default since JAX 0.5.0).
//   k1, k2 = split(key(1));  lower = random_bits(k2, 32, (8,));  idx = lower & 0xFFFF
//   split:       newkey_j = threefry2x32((0,1), (0, j))
//   random_bits: bits[b]  = o0 ^ o1 of threefry2x32(k2, (0, b))
// ---------------------------------------------------------------------------
static void threefry2x32_host(uint32_t k0, uint32_t k1, uint32_t c0, uint32_t c1,
                              uint32_t* o0, uint32_t* o1) {
    const uint32_t ks[3] = { k0, k1, k0 ^ k1 ^ 0x1BD11BDAu };
    static const int rot0[4] = {13, 15, 26, 6};
    static const int rot1[4] = {17, 29, 16, 24};
    uint32_t x0 = c0 + ks[0];
    uint32_t x1 = c1 + ks[1];
    for (int i = 0; i < 5; ++i) {
        const int* rr = (i % 2 == 0) ? rot0 : rot1;
        for (int j = 0; j < 4; ++j) {
            x0 += x1;
            x1 = (x1 << rr[j]) | (x1 >> (32 - rr[j]));
            x1 ^= x0;
        }
        x0 += ks[(i + 1) % 3];
        x1 += ks[(i + 2) % 3] + (uint32_t)(i + 1);
    }
    *o0 = x0; *o1 = x1;
}

extern "C" void kernel_launch(void* const* d_in, const int* in_sizes, int n_in,
                              void* d_out, int out_size) {
    (void)in_sizes; (void)n_in; (void)out_size;
    const float* xyz  = (const float*)d_in[0];
    const float* feat = (const float*)d_in[1];

    uint32_t k2a, k2b;
    threefry2x32_host(0u, 1u, 0u, 1u, &k2a, &k2b);   // k2 = second split of key(1)

    InitFar init;
    for (int b = 0; b < BB; ++b) {
        uint32_t o0, o1;
        threefry2x32_host(k2a, k2b, 0u, (uint32_t)b, &o0, &o1);
        init.v[b] = (int)((o0 ^ o1) & 0xFFFFu);
    }

    init_kernel<<<256, 256>>>();
    fps_kernel<<<dim3(CHUNKS, BB), TFPS>>>(xyz, init);
    gather_kernel<<<dim3(BB, CC), 256>>>(xyz, feat, (float*)d_out);
}

// round 6
// speedup vs baseline: 1.2308x; 1.2308x over previous
#include <cuda_runtime.h>
#include <cstdint>

// Problem constants (from reference): B=8, N=65536, C=256, NPOINT=1024
#define BB        8
#define NN        65536
#define CC        256
#define NPOINTS   1024
#define CHUNKS    16                  // CTAs per batch == cluster size
#define TFPS      512                 // threads per FPS block
#define NWARP     (TFPS / 32)
#define PPB       (NN / CHUNKS)       // 4096 points per block
#define PPT       (PPB / TFPS)        // 8 points per thread

__device__ int g_inds[BB][NPOINTS];   // fully rewritten every run -> no init needed

struct InitFar { int v[BB]; };

// ---------------------------------------------------------------------------
// PTX helpers
// ---------------------------------------------------------------------------
__device__ __forceinline__ uint32_t smem_u32(const void* p) {
    uint32_t a;
    asm("{ .reg .u64 t; cvta.to.shared.u64 t, %1; cvt.u32.u64 %0, t; }" : "=r"(a) : "l"(p));
    return a;
}
__device__ __forceinline__ uint32_t my_ctarank() {
    uint32_t r; asm("mov.u32 %0, %%cluster_ctarank;" : "=r"(r)); return r;
}
__device__ __forceinline__ uint32_t mapa_u32(uint32_t local, uint32_t rank) {
    uint32_t r;
    asm("mapa.shared::cluster.u32 %0, %1, %2;" : "=r"(r) : "r"(local), "r"(rank));
    return r;
}
__device__ __forceinline__ void st_dsmem_u64(uint32_t addr, unsigned long long v) {
    asm volatile("st.relaxed.cluster.shared::cluster.u64 [%0], %1;" :: "r"(addr), "l"(v) : "memory");
}
__device__ __forceinline__ unsigned long long ld_smem_relaxed_u64(uint32_t addr) {
    unsigned long long v;
    asm volatile("ld.relaxed.cluster.shared::cta.u64 %0, [%1];" : "=l"(v) : "r"(addr) : "memory");
    return v;
}
__device__ __forceinline__ void cluster_sync_all() {
    asm volatile("barrier.cluster.arrive.aligned;" ::: "memory");
    asm volatile("barrier.cluster.wait.aligned;"   ::: "memory");
}

// ---------------------------------------------------------------------------
// FPS: one batch = one 16-CTA cluster. Points + running distances live in
// registers. Per iteration: local argmax -> warp reduce -> block combine in
// warp 0 -> all-to-all publish via DSMEM stores (16 lanes, one peer each) ->
// each CTA polls its OWN smem slots (LDS-latency detection) -> local 16-way
// max -> broadcast. Zero global-memory traffic on the critical path.
//
// Packed value: (dist_bits << 32) | ((~idx & 0x7FFFFFFF) | phase<<31).
// dist >= 0 -> float bit pattern is order-preserving; within an iteration all
// values share the phase bit, so u64-max == (max dist, then smallest idx) ==
// jnp.argmax first-occurrence tie-break. Phase tag ((it>>1)&1) + double
// buffering (it&1) makes stale values self-identifying: a peer can be at most
// one iteration ahead (its it+1 publish requires our it publish), so the only
// possible residents of a slot are iterations it and it-2, whose tags differ.
// ---------------------------------------------------------------------------
__global__ __launch_bounds__(TFPS, 1) __cluster_dims__(CHUNKS, 1, 1)
void fps_kernel(const float* __restrict__ xyz, InitFar init) {
    const int b    = blockIdx.y;
    const int t    = threadIdx.x;
    const int lane = t & 31;
    const int warp = t >> 5;
    const uint32_t rank = my_ctarank();          // == blockIdx.x
    const int base = (int)rank * PPB;

    __shared__ unsigned long long s_slots[2][CHUNKS];
    __shared__ unsigned long long s_red[NWARP];
    __shared__ int s_far;

    // Init mailbox slots with phase-tag 1 (iters 0/1 expect tag 0 -> invalid)
    if (t < 2 * CHUNKS) s_slots[t >> 4][t & 15] = 0x80000000ull;

    const float* __restrict__ xb = xyz + (size_t)b * NN * 3;

    float    px[PPT], py[PPT], pz[PPT], dist[PPT];
    unsigned ienc[PPT];
#pragma unroll
    for (int k = 0; k < PPT; ++k) {
        const int p = base + k * TFPS + t;
        const float* q = xb + 3 * (size_t)p;
        px[k] = q[0]; py[k] = q[1]; pz[k] = q[2];
        dist[k] = 1e10f;
        ienc[k] = ~(unsigned)p;
    }

    // Precompute DSMEM addresses (warp 0 only uses them)
    uint32_t st_addr[2], poll_addr[2];
    {
        const uint32_t l0 = smem_u32(&s_slots[0][rank]);
        const uint32_t l1 = smem_u32(&s_slots[1][rank]);
        const uint32_t peer = (lane < CHUNKS) ? (uint32_t)lane : 0u;
        st_addr[0] = mapa_u32(l0, peer);          // write my value into peer's slot[buf][rank]
        st_addr[1] = mapa_u32(l1, peer);
        poll_addr[0] = smem_u32(&s_slots[0][lane & 15]);  // read my own slot[buf][lane]
        poll_addr[1] = smem_u32(&s_slots[1][lane & 15]);
    }

    __syncthreads();
    cluster_sync_all();   // all CTAs' slots initialized before any peer publish

    int far = init.v[b];

    for (int it = 0; it < NPOINTS; ++it) {
        const int buf = it & 1;
        const unsigned phase = (unsigned)((it >> 1) & 1);

        if (rank == 0 && t == 0) g_inds[b][it] = far;   // lax.scan records pre-update index

        const float* cq = xb + 3 * (size_t)far;
        const float cx = __ldg(cq + 0);
        const float cy = __ldg(cq + 1);
        const float cz = __ldg(cq + 2);

        float    bd = -1.0f;
        unsigned bi = 0u;
#pragma unroll
        for (int k = 0; k < PPT; ++k) {
            // Match XLA (no FP contraction): sub, mul, (d0+d1)+d2, all RN
            const float dx = __fsub_rn(px[k], cx);
            const float dy = __fsub_rn(py[k], cy);
            const float dz = __fsub_rn(pz[k], cz);
            const float d  = __fadd_rn(__fadd_rn(__fmul_rn(dx, dx), __fmul_rn(dy, dy)),
                                       __fmul_rn(dz, dz));
            const float nd = fminf(dist[k], d);
            dist[k] = nd;
            if (nd > bd) { bd = nd; bi = ienc[k]; }     // strict > keeps smallest idx
        }

        unsigned long long pk =
            ((unsigned long long)__float_as_uint(bd) << 32)
            | (unsigned long long)((bi & 0x7FFFFFFFu) | (phase << 31));

        // Warp reduce (max)
#pragma unroll
        for (int off = 16; off > 0; off >>= 1) {
            const unsigned long long o = __shfl_xor_sync(0xFFFFFFFFu, pk, off);
            pk = (pk < o) ? o : pk;
        }
        if (lane == 0) s_red[warp] = pk;
        __syncthreads();

        if (warp == 0) {
            // Block combine: 16 warp results -> butterfly max
            unsigned long long blk = (lane < NWARP) ? s_red[lane] : 0ull;
#pragma unroll
            for (int off = 16; off > 0; off >>= 1) {
                const unsigned long long o = __shfl_xor_sync(0xFFFFFFFFu, blk, off);
                blk = (blk < o) ? o : blk;
            }

            // Publish: lane r sends this block's value into CTA r's slot[buf][rank]
            if (lane < CHUNKS) st_dsmem_u64(st_addr[buf], blk);

            // Poll own slots: lane r watches slot[buf][r] (LDS-latency rounds)
            unsigned long long v = 0ull;
            bool done = (lane >= CHUNKS);
            for (;;) {
                if (!done) {
                    v = ld_smem_relaxed_u64(poll_addr[buf]);
                    done = (((unsigned)(v >> 31)) & 1u) == phase;
                }
                if (__ballot_sync(0xFFFFFFFFu, done) == 0xFFFFFFFFu) break;
            }
            if (lane >= CHUNKS) v = 0ull;
#pragma unroll
            for (int off = 16; off > 0; off >>= 1) {
                const unsigned long long o = __shfl_xor_sync(0xFFFFFFFFu, v, off);
                v = (v < o) ? o : v;
            }
            if (lane == 0) s_far = (int)((~(unsigned)(v & 0xFFFFFFFFull)) & 0xFFFFu);
        }
        __syncthreads();
        far = s_far;
    }

    cluster_sync_all();   // no CTA exits while peers might still address its SMEM
}

// ---------------------------------------------------------------------------
// Gather outputs. d_out (float32) layout, concatenated in reference order:
//   [0)                    new_xyz      (B, NPOINT, 3)
//   [B*NPOINT*3)           new_features (B, C, NPOINT)
//   [.. + B*C*NPOINT)      sample_inds  (B, NPOINT)  (indices as float)
// ---------------------------------------------------------------------------
__global__ void gather_kernel(const float* __restrict__ xyz,
                              const float* __restrict__ feat,
                              float* __restrict__ out) {
    const int b = blockIdx.x;
    const int c = blockIdx.y;

    float* out_xyz  = out;
    float* out_feat = out + (size_t)BB * NPOINTS * 3;
    float* out_inds = out_feat + (size_t)BB * CC * NPOINTS;

    const float* frow = feat + ((size_t)b * CC + c) * NN;
    float*       orow = out_feat + ((size_t)b * CC + c) * NPOINTS;

    for (int j = threadIdx.x; j < NPOINTS; j += blockDim.x) {
        const int idx = g_inds[b][j];
        orow[j] = frow[idx];
        if (c == 0) {
            out_inds[(size_t)b * NPOINTS + j] = (float)idx;
            const float* q = xyz + ((size_t)b * NN + idx) * 3;
            float* o = out_xyz + ((size_t)b * NPOINTS + j) * 3;
            o[0] = q[0]; o[1] = q[1]; o[2] = q[2];
        }
    }
}

// ---------------------------------------------------------------------------
// Host: reproduce jax.random.randint(jax.random.key(1), (8,), 0, 65536)
// under jax_threefry_partitionable=True (default since JAX 0.5.0).
//   k1, k2 = split(key(1));  lower = random_bits(k2, 32, (8,));  idx = lower & 0xFFFF
//   split:       newkey_j = threefry2x32((0,1), (0, j))
//   random_bits: bits[b]  = o0 ^ o1 of threefry2x32(k2, (0, b))
// ---------------------------------------------------------------------------
static void threefry2x32_host(uint32_t k0, uint32_t k1, uint32_t c0, uint32_t c1,
                              uint32_t* o0, uint32_t* o1) {
    const uint32_t ks[3] = { k0, k1, k0 ^ k1 ^ 0x1BD11BDAu };
    static const int rot0[4] = {13, 15, 26, 6};
    static const int rot1[4] = {17, 29, 16, 24};
    uint32_t x0 = c0 + ks[0];
    uint32_t x1 = c1 + ks[1];
    for (int i = 0; i < 5; ++i) {
        const int* rr = (i % 2 == 0) ? rot0 : rot1;
        for (int j = 0; j < 4; ++j) {
            x0 += x1;
            x1 = (x1 << rr[j]) | (x1 >> (32 - rr[j]));
            x1 ^= x0;
        }
        x0 += ks[(i + 1) % 3];
        x1 += ks[(i + 2) % 3] + (uint32_t)(i + 1);
    }
    *o0 = x0; *o1 = x1;
}

extern "C" void kernel_launch(void* const* d_in, const int* in_sizes, int n_in,
                              void* d_out, int out_size) {
    (void)in_sizes; (void)n_in; (void)out_size;
    const float* xyz  = (const float*)d_in[0];
    const float* feat = (const float*)d_in[1];

    uint32_t k2a, k2b;
    threefry2x32_host(0u, 1u, 0u, 1u, &k2a, &k2b);   // k2 = second split of key(1)

    InitFar init;
    for (int b = 0; b < BB; ++b) {
        uint32_t o0, o1;
        threefry2x32_host(k2a, k2b, 0u, (uint32_t)b, &o0, &o1);
        init.v[b] = (int)((o0 ^ o1) & 0xFFFFu);
    }

    // 16-CTA clusters require the non-portable opt-in (idempotent, not captured)
    cudaFuncSetAttribute(fps_kernel, cudaFuncAttributeNonPortableClusterSizeAllowed, 1);

    fps_kernel<<<dim3(CHUNKS, BB), TFPS>>>(xyz, init);
    gather_kernel<<<dim3(BB, CC), 256>>>(xyz, feat, (float*)d_out);
}